// round 2
// baseline (speedup 1.0000x reference)
#include <cuda_runtime.h>
#include <cuda_bf16.h>

#define FULL 0xFFFFFFFFu

__device__ __forceinline__ void ce(float& a, float& b) {
    float hi = fmaxf(a, b);
    float lo = fminf(a, b);
    a = hi; b = lo;
}

// One warp per row. Row layout:
//   corners[row*132]: 4 groups of 33 logits -> softmax -> sorted top4 + mean -> stat[20]
//   quality = W2^T relu(W1^T stat + b1) + b2  (scalar)
//   out[row*80 + c] = scores[row*80 + c] + quality
__global__ __launch_bounds__(256)
void lqe_kernel(const float* __restrict__ scores,
                const float* __restrict__ corners,
                const float* __restrict__ W1,
                const float* __restrict__ b1,
                const float* __restrict__ W2,
                const float* __restrict__ b2,
                float* __restrict__ out,
                int rows)
{
    __shared__ float sW1[20 * 64];
    __shared__ float sb1[64];
    __shared__ float sW2[64];
    __shared__ float sb2;
    __shared__ float scorn[8][160];   // per-warp: 4 groups, stride 40 (33 used) -> conflict-free reads

    const int tid = threadIdx.x;
    for (int i = tid; i < 1280; i += 256) sW1[i] = W1[i];
    if (tid < 64) { sb1[tid] = b1[tid]; sW2[tid] = W2[tid]; }
    if (tid == 0) sb2 = b2[0];
    __syncthreads();

    const int warp = tid >> 5;
    const int lane = tid & 31;
    const int sub  = lane >> 3;   // softmax group 0..3
    const int j    = lane & 7;    // lane within group
    float* sw = scorn[warp];

    const int gw0  = blockIdx.x * 8 + warp;
    const int step = gridDim.x * 8;

    for (int row = gw0; row < rows; row += step) {
        const float* cr = corners + (size_t)row * 132;

        // ---- stage 132 logits coalesced -> padded shared layout [g*40 + b] ----
        #pragma unroll
        for (int k = 0; k < 4; k++) {
            int i = lane + 32 * k;
            float v = cr[i];
            int g = i / 33;
            sw[g * 40 + (i - 33 * g)] = v;
        }
        if (lane < 4) {
            int i = 128 + lane;          // 128..131, all group 3
            sw[3 * 40 + (i - 99)] = cr[i];
        }
        __syncwarp();

        // ---- per-lane values of its group (8 lanes x ~4-5 bins each) ----
        float v0 = sw[40 * sub + j];
        float v1 = sw[40 * sub + j + 8];
        float v2 = sw[40 * sub + j + 16];
        float v3 = sw[40 * sub + j + 24];
        float v4 = (j == 0) ? sw[40 * sub + 32] : -1e30f;
        __syncwarp();  // reads done before next iteration restages

        // group max (butterfly within 8-lane subgroup)
        float m = fmaxf(fmaxf(v0, v1), fmaxf(v2, fmaxf(v3, v4)));
        m = fmaxf(m, __shfl_xor_sync(FULL, m, 1));
        m = fmaxf(m, __shfl_xor_sync(FULL, m, 2));
        m = fmaxf(m, __shfl_xor_sync(FULL, m, 4));

        float e0 = __expf(v0 - m);
        float e1 = __expf(v1 - m);
        float e2 = __expf(v2 - m);
        float e3 = __expf(v3 - m);
        float e4 = (j == 0) ? __expf(v4 - m) : 0.0f;

        float s = e0 + e1 + e2 + e3 + e4;
        s += __shfl_xor_sync(FULL, s, 1);
        s += __shfl_xor_sync(FULL, s, 2);
        s += __shfl_xor_sync(FULL, s, 4);

        // ---- local sorted top4 (desc) of this lane's exp values ----
        float t0 = e0, t1 = e1, t2 = e2, t3 = e3;
        ce(t0, t1); ce(t2, t3); ce(t0, t2); ce(t1, t3); ce(t1, t2);
        {   // insert 5th value (sentinel -1 for lanes without one; exps are >= 0)
            float x = (j == 0) ? e4 : -1.0f;
            float c;
            float n0 = fmaxf(t0, x); c = fminf(t0, x);
            float n1 = fmaxf(t1, c); c = fminf(t1, c);
            float n2 = fmaxf(t2, c); c = fminf(t2, c);
            float n3 = fmaxf(t3, c);
            t0 = n0; t1 = n1; t2 = n2; t3 = n3;
        }

        // ---- butterfly merge of sorted quads across 8-lane subgroup ----
        // bitonic split: u_i = max(a_i, b_{3-i}) contains the top4 of both quads
        #pragma unroll
        for (int off = 1; off <= 4; off <<= 1) {
            float o0 = __shfl_xor_sync(FULL, t0, off);
            float o1 = __shfl_xor_sync(FULL, t1, off);
            float o2 = __shfl_xor_sync(FULL, t2, off);
            float o3 = __shfl_xor_sync(FULL, t3, off);
            float u0 = fmaxf(t0, o3);
            float u1 = fmaxf(t1, o2);
            float u2 = fmaxf(t2, o1);
            float u3 = fmaxf(t3, o0);
            ce(u0, u2); ce(u1, u3); ce(u0, u1); ce(u2, u3);
            t0 = u0; t1 = u1; t2 = u2; t3 = u3;
        }

        // ---- broadcast per-group stats to all lanes: stat[5g+t] ----
        float st[20];
        #pragma unroll
        for (int g = 0; g < 4; g++) {
            float S   = __shfl_sync(FULL, s,  8 * g);
            float inv = __frcp_rn(S);
            float p0 = __shfl_sync(FULL, t0, 8 * g) * inv;
            float p1 = __shfl_sync(FULL, t1, 8 * g) * inv;
            float p2 = __shfl_sync(FULL, t2, 8 * g) * inv;
            float p3 = __shfl_sync(FULL, t3, 8 * g) * inv;
            st[5 * g + 0] = p0;
            st[5 * g + 1] = p1;
            st[5 * g + 2] = p2;
            st[5 * g + 3] = p3;
            st[5 * g + 4] = 0.25f * (p0 + p1 + p2 + p3);
        }

        // ---- MLP: lane owns hidden units lane and lane+32 ----
        float h0 = sb1[lane], h1 = sb1[lane + 32];
        #pragma unroll
        for (int d = 0; d < 20; d++) {
            h0 += st[d] * sW1[d * 64 + lane];
            h1 += st[d] * sW1[d * 64 + lane + 32];
        }
        h0 = fmaxf(h0, 0.0f);
        h1 = fmaxf(h1, 0.0f);
        float q = h0 * sW2[lane] + h1 * sW2[lane + 32];
        #pragma unroll
        for (int off = 16; off >= 1; off >>= 1)
            q += __shfl_xor_sync(FULL, q, off);
        q += sb2;

        // ---- output: 80 floats = 20 float4, lanes 0..19 ----
        const float4* s4 = (const float4*)(scores + (size_t)row * 80);
        float4*       o4 = (float4*)(out + (size_t)row * 80);
        if (lane < 20) {
            float4 v = s4[lane];
            v.x += q; v.y += q; v.z += q; v.w += q;
            o4[lane] = v;
        }
    }
}

extern "C" void kernel_launch(void* const* d_in, const int* in_sizes, int n_in,
                              void* d_out, int out_size) {
    const float* scores  = (const float*)d_in[0];
    const float* corners = (const float*)d_in[1];
    const float* W1      = (const float*)d_in[2];
    const float* b1      = (const float*)d_in[3];
    const float* W2      = (const float*)d_in[4];
    const float* b2      = (const float*)d_in[5];
    float* out = (float*)d_out;

    int rows = in_sizes[0] / 80;          // B*L = 524288
    int blocks = (rows + 7) / 8;
    if (blocks > 4096) blocks = 4096;     // grid-stride: ~16 rows per warp
    lqe_kernel<<<blocks, 256>>>(scores, corners, W1, b1, W2, b2, out, rows);
}